// round 13
// baseline (speedup 1.0000x reference)
#include <cuda_runtime.h>
#include <cuda_fp16.h>

// ---------------------------------------------------------------------------
// Problem shape (fixed by setup_inputs)
// ---------------------------------------------------------------------------
#define B_ 8
#define T_ 2048
#define D_ 2048
#define M_ (B_ * T_)   // 16384 rows

__device__ float  g_P [(size_t)M_ * (size_t)D_];   // P = x @ Wp^T + bp
__device__ __half g_Xh[(size_t)M_ * (size_t)D_];   // fp16 copy of x
__device__ __half g_Wh[(size_t)D_ * (size_t)D_];   // fp16 copy of Wp

// ---------------------------------------------------------------------------
// helpers
// ---------------------------------------------------------------------------
__device__ __forceinline__ unsigned pack_f16(float lo, float hi) {
    unsigned r;
    asm("cvt.rn.f16x2.f32 %0, %1, %2;" : "=r"(r) : "f"(hi), "f"(lo));  // 1st src = upper
    return r;
}
// fp16-accumulate HMMA: D,C are 2 regs (4 halves). The experiment: is this 2x rate?
__device__ __forceinline__ void mma_f16acc(unsigned* c, const unsigned* a, const unsigned* b) {
    asm volatile(
        "mma.sync.aligned.m16n8k16.row.col.f16.f16.f16.f16 "
        "{%0,%1}, {%2,%3,%4,%5}, {%6,%7}, {%0,%1};"
        : "+r"(c[0]), "+r"(c[1])
        : "r"(a[0]), "r"(a[1]), "r"(a[2]), "r"(a[3]), "r"(b[0]), "r"(b[1]));
}

__device__ __forceinline__ unsigned smem_u32(const void* p) {
    unsigned a;
    asm("{ .reg .u64 t; cvta.to.shared.u64 t, %1; cvt.u32.u64 %0, t; }" : "=r"(a) : "l"(p));
    return a;
}
__device__ __forceinline__ void cp8(unsigned dst, const void* src) {
    asm volatile("cp.async.ca.shared.global [%0], [%1], 8;" :: "r"(dst), "l"(src) : "memory");
}
__device__ __forceinline__ void cp16(unsigned dst, const void* src) {
    asm volatile("cp.async.ca.shared.global [%0], [%1], 16;" :: "r"(dst), "l"(src) : "memory");
}
#define CP_COMMIT() asm volatile("cp.async.commit_group;" ::: "memory")
#define CP_WAIT(n)  asm volatile("cp.async.wait_group %0;" :: "n"(n) : "memory")

// ---------------------------------------------------------------------------
// One-shot fp32 -> fp16 conversion (HBM-bound). Word = (k, k+1), k in low half.
// ---------------------------------------------------------------------------
__global__ __launch_bounds__(256)
void convert_f16_kernel(const float* __restrict__ src, __half* __restrict__ dst) {
    const size_t i = ((size_t)blockIdx.x * 256 + threadIdx.x) * 4;
    const float4 v = *reinterpret_cast<const float4*>(src + i);
    *reinterpret_cast<uint2*>(dst + i) =
        make_uint2(pack_f16(v.x, v.y), pack_f16(v.z, v.w));
}

// ---------------------------------------------------------------------------
// GEMM: P[m][n] = sum_k X[m][k]*W[n][k] + bias[n]   (TN, fp16 inputs)
// CTA 128x256, K-chunk 32, 512 thr, warp grid 2(M)x8(N), warp tile 64x32.
// fp16 accumulation chained over K=64 windows (2 chunks), dumped to fp32.
// SMEM image: validated R11/R12 permuted-fragment layout (fp16 words).
// Producer: cp.async from preconverted fp16 gmem (zero staging registers).
// ---------------------------------------------------------------------------
#define BM 128
#define BN 256
#define KB 32
#define NCHUNK (D_ / KB)          // 64
#define A_KS 1032                 // words per 16-k A block (8 mtiles*128 + 8 pad)
#define B_KS 2056                 // words per 16-k B block (32 ntiles*64 + 8 pad)
#define OFF_Bw (2 * A_KS)         // 2064 words
#define STAGEW (OFF_Bw + 2 * B_KS)       // 6176 words (24704 B) per stage
#define NSTAGE 3
#define SMEM_BYTES (NSTAGE * STAGEW * 4) // 74112 B

__global__ __launch_bounds__(512, 1)
void braid_gemm_mma(const __half* __restrict__ Xh,
                    const __half* __restrict__ Wh,
                    const float* __restrict__ bias,
                    float* __restrict__ P) {
    extern __shared__ __align__(16) unsigned smem[];
    const unsigned sb = smem_u32(smem);
    const int tid  = threadIdx.x;
    const int lane = tid & 31;
    const int wrp  = tid >> 5;          // 0..15
    const int wm   = wrp >> 3;          // 0..1  (64 M rows)
    const int wn   = wrp & 7;           // 0..7  (32 N cols)
    const int bm   = blockIdx.y * BM;
    const int bn   = blockIdx.x * BN;

    const __half* Xb = Xh + (size_t)bm * D_;
    const __half* Wb = Wh + (size_t)bn * D_;

    float acc[4][4][4];                 // fp32 master
    unsigned acc16[4][4][2];            // fp16 window accumulator (f16x2 pairs)
#pragma unroll
    for (int q = 0; q < 4; q++)
#pragma unroll
        for (int p = 0; p < 4; p++) {
#pragma unroll
            for (int e = 0; e < 4; e++) acc[q][p][e] = 0.0f;
            acc16[q][p][0] = 0u; acc16[q][p][1] = 0u;
        }

    // ---- cp.async producer: chunk c into stage s ----
    auto issue_chunk = [&](int c, int s) {
        const int k0 = c * KB;
        const unsigned stage = sb + (unsigned)(s * STAGEW) * 4u;
        {                                               // A: 512 uint4 / 512 thr
            const int f   = tid;
            const int row = f >> 2, c8 = f & 3;
            const int ks  = c8 >> 1, cA = c8 & 1;
            const int mt  = row >> 4, r = row & 7, hf = (row >> 3) & 1;
            const unsigned w0 =
                (unsigned)(ks * A_KS + mt * 128 + hf * 2 + (r * 4 + 2 * cA) * 4);
            const __half* src = Xb + (size_t)row * D_ + k0 + c8 * 8;
            cp8(stage + w0 * 4u, src);
            cp8(stage + (w0 + 4) * 4u, src + 4);
        }
#pragma unroll
        for (int i = 0; i < 2; i++) {                   // B: 1024 uint4 / 512 thr
            const int f   = tid + i * 512;
            const int row = f >> 2, c8 = f & 3;
            const int ks  = c8 >> 1, cA = c8 & 1;
            const int nt  = row >> 3, n = row & 7;
            const unsigned w0 = (unsigned)(OFF_Bw + ks * B_KS + nt * 64 + n * 8 + cA * 4);
            cp16(stage + w0 * 4u, Wb + (size_t)row * D_ + k0 + c8 * 8);
        }
        CP_COMMIT();
    };

    // ---- MMA over stage s (2 k-steps of 16), fp16 accumulate ----
    auto mma_chunk = [&](int s) {
        const unsigned* As = smem + s * STAGEW;
        const unsigned* Bs = As + OFF_Bw;
#pragma unroll
        for (int ks = 0; ks < 2; ks++) {
            unsigned a[4][4], b[4][2];
#pragma unroll
            for (int q = 0; q < 4; q++) {
                uint4 v = *reinterpret_cast<const uint4*>(
                    As + ks * A_KS + (wm * 4 + q) * 128 + lane * 4);
                a[q][0] = v.x; a[q][1] = v.z; a[q][2] = v.y; a[q][3] = v.w;  // perm fixup
            }
#pragma unroll
            for (int p = 0; p < 4; p++) {
                uint2 v = *reinterpret_cast<const uint2*>(
                    Bs + ks * B_KS + (wn * 4 + p) * 64 + lane * 2);
                b[p][0] = v.x; b[p][1] = v.y;
            }
#pragma unroll
            for (int q = 0; q < 4; q++)
#pragma unroll
                for (int p = 0; p < 4; p++)
                    mma_f16acc(acc16[q][p], a[q], b[p]);
        }
    };

    // ---- dump fp16 window into fp32 master, reset window ----
    auto dump_window = [&]() {
#pragma unroll
        for (int q = 0; q < 4; q++)
#pragma unroll
            for (int p = 0; p < 4; p++) {
                const float2 f0 = __half22float2(
                    *reinterpret_cast<const __half2*>(&acc16[q][p][0]));
                const float2 f1 = __half22float2(
                    *reinterpret_cast<const __half2*>(&acc16[q][p][1]));
                acc[q][p][0] += f0.x; acc[q][p][1] += f0.y;
                acc[q][p][2] += f1.x; acc[q][p][3] += f1.y;
                acc16[q][p][0] = 0u; acc16[q][p][1] = 0u;
            }
    };

    // ---- pipeline: 3 stages, depth-2 prefetch, one barrier per chunk ----
    issue_chunk(0, 0);
    issue_chunk(1, 1);

    for (int c = 0; c < NCHUNK; c++) {
        CP_WAIT(1);                 // chunk c landed (this thread's copies)
        __syncthreads();            // all copies visible; all warps past mma(c-1)
        if (c + 2 < NCHUNK) issue_chunk(c + 2, (c + 2) % NSTAGE);  // stage held c-1
        else CP_COMMIT();           // empty group: uniform wait semantics
        mma_chunk(c % NSTAGE);
        if (c & 1) dump_window();   // K=64 window -> fp32 (accuracy-critical)
    }

    // ---- epilogue: bias + store ----
#pragma unroll
    for (int q = 0; q < 4; q++) {
        const int gr = bm + wm * 64 + q * 16 + (lane >> 2);
#pragma unroll
        for (int p = 0; p < 4; p++) {
            const int gc = bn + wn * 32 + p * 8 + (lane & 3) * 2;
            const float2 bv = *reinterpret_cast<const float2*>(bias + gc);
            float2 o0 = make_float2(acc[q][p][0] + bv.x, acc[q][p][1] + bv.y);
            float2 o1 = make_float2(acc[q][p][2] + bv.x, acc[q][p][3] + bv.y);
            *reinterpret_cast<float2*>(&P[(size_t)gr * D_ + gc])       = o0;
            *reinterpret_cast<float2*>(&P[(size_t)(gr + 8) * D_ + gc]) = o1;
        }
    }
}

// ---------------------------------------------------------------------------
// LN epilogue (at HBM roofline — unchanged). One block per row r = b*T + t.
//   t == 0    : out = LN(x + P[r+1]/6)
//   t == T-1  : out = LN(x + P[r-1]/6)
//   else      : out = LN( LN(x + P[r-1]/6) + P[r+1]/6 )
// ---------------------------------------------------------------------------
__device__ __forceinline__ float block_reduce_sum(float v, float* sbuf) {
#pragma unroll
    for (int o = 16; o > 0; o >>= 1) v += __shfl_xor_sync(0xffffffffu, v, o);
    const int w = threadIdx.x >> 5;
    if ((threadIdx.x & 31) == 0) sbuf[w] = v;
    __syncthreads();
    if (threadIdx.x < 32) {
        float r = (threadIdx.x < 8) ? sbuf[threadIdx.x] : 0.0f;
#pragma unroll
        for (int o = 4; o > 0; o >>= 1) r += __shfl_xor_sync(0xffffffffu, r, o);
        if (threadIdx.x == 0) sbuf[8] = r;
    }
    __syncthreads();
    return sbuf[8];
}

__global__ __launch_bounds__(256)
void braid_epilogue_kernel(const float* __restrict__ X,
                           const float* __restrict__ P,
                           const float* __restrict__ gamma,
                           const float* __restrict__ beta,
                           float* __restrict__ out) {
    __shared__ float sbuf[9];
    const int r = blockIdx.x;
    const int t = r & (T_ - 1);
    const int tid = threadIdx.x;
    const float inv6 = 1.0f / 6.0f;
    const float invD = 1.0f / (float)D_;

    const size_t base = (size_t)r * D_;
    const int d0 = tid * 4, d1 = 1024 + tid * 4;

    float v[8], g[8], be[8];
    {
        const float4 ga = *reinterpret_cast<const float4*>(gamma + d0);
        const float4 gb = *reinterpret_cast<const float4*>(gamma + d1);
        const float4 ba = *reinterpret_cast<const float4*>(beta + d0);
        const float4 bb = *reinterpret_cast<const float4*>(beta + d1);
        g[0]=ga.x; g[1]=ga.y; g[2]=ga.z; g[3]=ga.w; g[4]=gb.x; g[5]=gb.y; g[6]=gb.z; g[7]=gb.w;
        be[0]=ba.x; be[1]=ba.y; be[2]=ba.z; be[3]=ba.w; be[4]=bb.x; be[5]=bb.y; be[6]=bb.z; be[7]=bb.w;
    }
    {
        const size_t nb = (t == 0) ? base + D_ : base - D_;
        const float4 xa = *reinterpret_cast<const float4*>(X + base + d0);
        const float4 xb = *reinterpret_cast<const float4*>(X + base + d1);
        const float4 pa = *reinterpret_cast<const float4*>(P + nb + d0);
        const float4 pb = *reinterpret_cast<const float4*>(P + nb + d1);
        v[0]=xa.x+inv6*pa.x; v[1]=xa.y+inv6*pa.y; v[2]=xa.z+inv6*pa.z; v[3]=xa.w+inv6*pa.w;
        v[4]=xb.x+inv6*pb.x; v[5]=xb.y+inv6*pb.y; v[6]=xb.z+inv6*pb.z; v[7]=xb.w+inv6*pb.w;
    }
    {
        float s = 0.0f;
#pragma unroll
        for (int i = 0; i < 8; i++) s += v[i];
        const float mu = block_reduce_sum(s, sbuf) * invD;
        float q = 0.0f;
#pragma unroll
        for (int i = 0; i < 8; i++) { const float c = v[i] - mu; q += c * c; }
        const float rs = rsqrtf(block_reduce_sum(q, sbuf) * invD + 1e-5f);
#pragma unroll
        for (int i = 0; i < 8; i++) v[i] = (v[i] - mu) * rs * g[i] + be[i];
    }
    if (t != 0 && t != T_ - 1) {
        const size_t nb = base + D_;
        const float4 pa = *reinterpret_cast<const float4*>(P + nb + d0);
        const float4 pb = *reinterpret_cast<const float4*>(P + nb + d1);
        v[0]+=inv6*pa.x; v[1]+=inv6*pa.y; v[2]+=inv6*pa.z; v[3]+=inv6*pa.w;
        v[4]+=inv6*pb.x; v[5]+=inv6*pb.y; v[6]+=inv6*pb.z; v[7]+=inv6*pb.w;
        float s = 0.0f;
#pragma unroll
        for (int i = 0; i < 8; i++) s += v[i];
        const float mu = block_reduce_sum(s, sbuf) * invD;
        float q = 0.0f;
#pragma unroll
        for (int i = 0; i < 8; i++) { const float c = v[i] - mu; q += c * c; }
        const float rs = rsqrtf(block_reduce_sum(q, sbuf) * invD + 1e-5f);
#pragma unroll
        for (int i = 0; i < 8; i++) v[i] = (v[i] - mu) * rs * g[i] + be[i];
    }
    *reinterpret_cast<float4*>(out + base + d0) = make_float4(v[0], v[1], v[2], v[3]);
    *reinterpret_cast<float4*>(out + base + d1) = make_float4(v[4], v[5], v[6], v[7]);
}

// ---------------------------------------------------------------------------
// Launch. Inputs: x, W1, b1, W2, b2, Wp, bp, gamma, beta.
// W1/b1/W2/b2 dead: mean(softmax(logits)) over the softmax axis == 1/6 exactly.
// ---------------------------------------------------------------------------
extern "C" void kernel_launch(void* const* d_in, const int* in_sizes, int n_in,
                              void* d_out, int out_size) {
    const float* x     = (const float*)d_in[0];
    const float* Wp    = (const float*)d_in[5];
    const float* bp    = (const float*)d_in[6];
    const float* gamma = (const float*)d_in[7];
    const float* beta  = (const float*)d_in[8];
    float* out = (float*)d_out;

    float*  P;
    __half* Xh;
    __half* Wh;
    cudaGetSymbolAddress((void**)&P,  g_P);
    cudaGetSymbolAddress((void**)&Xh, g_Xh);
    cudaGetSymbolAddress((void**)&Wh, g_Wh);

    cudaFuncSetAttribute(braid_gemm_mma, cudaFuncAttributeMaxDynamicSharedMemorySize, SMEM_BYTES);

    convert_f16_kernel<<<(size_t)M_ * D_ / 1024, 256>>>(x,  Xh);
    convert_f16_kernel<<<(size_t)D_ * D_ / 1024, 256>>>(Wp, Wh);

    dim3 ggrid(D_ / BN, M_ / BM);   // (8, 128): x-fastest -> A-tile L2 reuse, W L2-resident
    braid_gemm_mma<<<ggrid, 512, SMEM_BYTES>>>(Xh, Wh, bp, P);
    braid_epilogue_kernel<<<M_, 256>>>(x, P, gamma, beta, out);
}

// round 14
// speedup vs baseline: 1.3447x; 1.3447x over previous
#include <cuda_runtime.h>
#include <cuda_fp16.h>

// ---------------------------------------------------------------------------
// Problem shape (fixed by setup_inputs)
// ---------------------------------------------------------------------------
#define B_ 8
#define T_ 2048
#define D_ 2048
#define M_ (B_ * T_)   // 16384 rows

__device__ __half g_Ph[(size_t)M_ * (size_t)D_];   // P = x @ Wp^T + bp (fp16)

// ---------------------------------------------------------------------------
// fp16 helpers. fp16 mantissa (11 bit) == tf32 mantissa -> tf32-class accuracy.
// ---------------------------------------------------------------------------
__device__ __forceinline__ unsigned pack_f16(float lo, float hi) {
    unsigned r;
    asm("cvt.rn.f16x2.f32 %0, %1, %2;" : "=r"(r) : "f"(hi), "f"(lo));  // 1st src = upper
    return r;
}
__device__ __forceinline__ void mma_f16(float* c, const unsigned* a, const unsigned* b) {
    asm volatile(
        "mma.sync.aligned.m16n8k16.row.col.f32.f16.f16.f32 "
        "{%0,%1,%2,%3}, {%4,%5,%6,%7}, {%8,%9}, {%0,%1,%2,%3};"
        : "+f"(c[0]), "+f"(c[1]), "+f"(c[2]), "+f"(c[3])
        : "r"(a[0]), "r"(a[1]), "r"(a[2]), "r"(a[3]), "r"(b[0]), "r"(b[1]));
}

// ---------------------------------------------------------------------------
// GEMM: P[m][n] = sum_k X[m][k]*W[n][k] + bias[n]   (TN, both K-contiguous)
// EXACT R11 config (measured at the m16n8k16 HMMA issue ceiling:
// 128 HMMA x 15.5 cyc = 1984 cyc/chunk/SMSP vs 1982 measured):
// CTA 128x256, K-chunk 32 (2 MMA k-steps of 16), 256 thr, 2x4 warps of 64x64,
// reg-staged producer with in-flight fp32->fp16 convert, double buffer,
// one barrier per chunk. Only change: P stored as fp16 (halves store traffic).
//
// k-permutation per 16-k step: fragment k-pair kp=c <-> phys pair 2c,
// kp=c+4 <-> phys pair 2c+1 (c = 0..3). A,B permute identically; k is a
// reduction axis -> exact.
// ---------------------------------------------------------------------------
#define BM 128
#define BN 256
#define KB 32
#define NCHUNK (D_ / KB)          // 64
#define A_KS 1032                 // words per 16-k A block (8 mtiles*128 + 8 pad)
#define B_KS 2056                 // words per 16-k B block (32 ntiles*64 + 8 pad)
#define OFF_Bw (2 * A_KS)         // 2064 words
#define STAGEW (OFF_Bw + 2 * B_KS)       // 6176 words (24704 B) per stage
#define SMEM_BYTES (2 * STAGEW * 4)      // 49408 B

__global__ __launch_bounds__(256, 1)
void braid_gemm_mma(const float* __restrict__ X,
                    const float* __restrict__ W,
                    const float* __restrict__ bias,
                    __half* __restrict__ P) {
    extern __shared__ __align__(16) unsigned smem[];
    const int tid  = threadIdx.x;
    const int lane = tid & 31;
    const int wrp  = tid >> 5;          // 0..7
    const int wm   = wrp >> 2;          // 0..1  (64 M rows)
    const int wn   = wrp & 3;           // 0..3  (64 N cols)
    const int bm   = blockIdx.y * BM;
    const int bn   = blockIdx.x * BN;

    const float* Xb = X + (size_t)bm * D_;
    const float* Wb = W + (size_t)bn * D_;

    float acc[4][8][4];
#pragma unroll
    for (int q = 0; q < 4; q++)
#pragma unroll
        for (int p = 0; p < 8; p++)
#pragma unroll
            for (int e = 0; e < 4; e++) acc[q][p][e] = 0.0f;

    float4 ar[4], br[8];

    // ---- gmem -> regs (coalesced float4) ----
    auto ldg_chunk = [&](int c) {
        const int k0 = c * KB;
#pragma unroll
        for (int i = 0; i < 4; i++) {                    // A: 1024 float4
            const int f = tid + i * 256;
            ar[i] = *reinterpret_cast<const float4*>(
                Xb + (size_t)(f >> 3) * D_ + k0 + (f & 7) * 4);
        }
#pragma unroll
        for (int i = 0; i < 8; i++) {                    // B: 2048 float4
            const int f = tid + i * 256;
            br[i] = *reinterpret_cast<const float4*>(
                Wb + (size_t)(f >> 3) * D_ + k0 + (f & 7) * 4);
        }
    };

    // ---- regs -> smem (fp16 convert, permuted fragment-major, STS.64 only) ----
    auto sts_chunk = [&](int s) {
        unsigned* As = smem + s * STAGEW;
        unsigned* Bs = As + OFF_Bw;
#pragma unroll
        for (int i = 0; i < 4; i++) {
            const int f   = tid + i * 256;
            const int row = f >> 3, c4 = f & 7;
            const int ks  = c4 >> 2, c = c4 & 3;
            const int mt  = row >> 4, r = row & 7, hf = (row >> 3) & 1;
            const int w0  = ks * A_KS + mt * 128 + (r * 4 + c) * 4 + hf * 2;
            *reinterpret_cast<uint2*>(As + w0) =
                make_uint2(pack_f16(ar[i].x, ar[i].y), pack_f16(ar[i].z, ar[i].w));
        }
#pragma unroll
        for (int i = 0; i < 8; i++) {
            const int f   = tid + i * 256;
            const int row = f >> 3, c4 = f & 7;
            const int ks  = c4 >> 2, c = c4 & 3;
            const int nt  = row >> 3, n = row & 7;
            const int w0  = ks * B_KS + nt * 64 + (n * 4 + c) * 2;
            *reinterpret_cast<uint2*>(Bs + w0) =
                make_uint2(pack_f16(br[i].x, br[i].y), pack_f16(br[i].z, br[i].w));
        }
    };

    // ---- MMA over stage s (2 k-steps of 16) ----
    auto mma_chunk = [&](int s) {
        const unsigned* As = smem + s * STAGEW;
        const unsigned* Bs = As + OFF_Bw;
#pragma unroll
        for (int ks = 0; ks < 2; ks++) {
            unsigned a[4][4], b[8][2];
#pragma unroll
            for (int q = 0; q < 4; q++) {
                uint4 v = *reinterpret_cast<const uint4*>(
                    As + ks * A_KS + (wm * 4 + q) * 128 + lane * 4);
                a[q][0] = v.x; a[q][1] = v.z; a[q][2] = v.y; a[q][3] = v.w;  // perm fixup
            }
#pragma unroll
            for (int p = 0; p < 8; p++) {
                uint2 v = *reinterpret_cast<const uint2*>(
                    Bs + ks * B_KS + (wn * 8 + p) * 64 + lane * 2);
                b[p][0] = v.x; b[p][1] = v.y;
            }
#pragma unroll
            for (int q = 0; q < 4; q++)
#pragma unroll
                for (int p = 0; p < 8; p++)
                    mma_f16(acc[q][p], a[q], b[p]);
        }
    };

    // ---- R11 schedule: double buffer, one barrier per chunk ----
    ldg_chunk(0);
    sts_chunk(0);
    __syncthreads();

    for (int c = 0; c < NCHUNK; c++) {
        const int s = c & 1;
        const bool more = (c + 1 < NCHUNK);
        if (more) ldg_chunk(c + 1);
        mma_chunk(s);
        if (more) {
            sts_chunk(s ^ 1);       // stage held chunk c-1: consumed before last barrier
            __syncthreads();
        }
    }

    // ---- epilogue: bias + fp16 store (halved traffic) ----
#pragma unroll
    for (int q = 0; q < 4; q++) {
        const int gr = bm + wm * 64 + q * 16 + (lane >> 2);
#pragma unroll
        for (int p = 0; p < 8; p++) {
            const int gc = bn + wn * 64 + p * 8 + (lane & 3) * 2;
            const float2 bv = *reinterpret_cast<const float2*>(bias + gc);
            *reinterpret_cast<unsigned*>(&P[(size_t)gr * D_ + gc]) =
                pack_f16(acc[q][p][0] + bv.x, acc[q][p][1] + bv.y);
            *reinterpret_cast<unsigned*>(&P[(size_t)(gr + 8) * D_ + gc]) =
                pack_f16(acc[q][p][2] + bv.x, acc[q][p][3] + bv.y);
        }
    }
}

// ---------------------------------------------------------------------------
// LN epilogue, P in fp16 (402 MB total vs 536 MB). One block per row r = b*T+t.
//   t == 0    : out = LN(x + P[r+1]/6)
//   t == T-1  : out = LN(x + P[r-1]/6)
//   else      : out = LN( LN(x + P[r-1]/6) + P[r+1]/6 )
// ---------------------------------------------------------------------------
__device__ __forceinline__ float block_reduce_sum(float v, float* sbuf) {
#pragma unroll
    for (int o = 16; o > 0; o >>= 1) v += __shfl_xor_sync(0xffffffffu, v, o);
    const int w = threadIdx.x >> 5;
    if ((threadIdx.x & 31) == 0) sbuf[w] = v;
    __syncthreads();
    if (threadIdx.x < 32) {
        float r = (threadIdx.x < 8) ? sbuf[threadIdx.x] : 0.0f;
#pragma unroll
        for (int o = 4; o > 0; o >>= 1) r += __shfl_xor_sync(0xffffffffu, r, o);
        if (threadIdx.x == 0) sbuf[8] = r;
    }
    __syncthreads();
    return sbuf[8];
}

// load 4 consecutive fp16 P values as floats
__device__ __forceinline__ float4 ldP4(const __half* p) {
    const uint2 u = *reinterpret_cast<const uint2*>(p);
    const float2 f0 = __half22float2(*reinterpret_cast<const __half2*>(&u.x));
    const float2 f1 = __half22float2(*reinterpret_cast<const __half2*>(&u.y));
    return make_float4(f0.x, f0.y, f1.x, f1.y);
}

__global__ __launch_bounds__(256)
void braid_epilogue_kernel(const float* __restrict__ X,
                           const __half* __restrict__ P,
                           const float* __restrict__ gamma,
                           const float* __restrict__ beta,
                           float* __restrict__ out) {
    __shared__ float sbuf[9];
    const int r = blockIdx.x;
    const int t = r & (T_ - 1);
    const int tid = threadIdx.x;
    const float inv6 = 1.0f / 6.0f;
    const float invD = 1.0f / (float)D_;

    const size_t base = (size_t)r * D_;
    const int d0 = tid * 4, d1 = 1024 + tid * 4;

    float v[8], g[8], be[8];
    {
        const float4 ga = *reinterpret_cast<const float4*>(gamma + d0);
        const float4 gb = *reinterpret_cast<const float4*>(gamma + d1);
        const float4 ba = *reinterpret_cast<const float4*>(beta + d0);
        const float4 bb = *reinterpret_cast<const float4*>(beta + d1);
        g[0]=ga.x; g[1]=ga.y; g[2]=ga.z; g[3]=ga.w; g[4]=gb.x; g[5]=gb.y; g[6]=gb.z; g[7]=gb.w;
        be[0]=ba.x; be[1]=ba.y; be[2]=ba.z; be[3]=ba.w; be[4]=bb.x; be[5]=bb.y; be[6]=bb.z; be[7]=bb.w;
    }
    {
        const size_t nb = (t == 0) ? base + D_ : base - D_;   // Pnext for t==0, else Pprev
        const float4 xa = *reinterpret_cast<const float4*>(X + base + d0);
        const float4 xb = *reinterpret_cast<const float4*>(X + base + d1);
        const float4 pa = ldP4(P + nb + d0);
        const float4 pb = ldP4(P + nb + d1);
        v[0]=xa.x+inv6*pa.x; v[1]=xa.y+inv6*pa.y; v[2]=xa.z+inv6*pa.z; v[3]=xa.w+inv6*pa.w;
        v[4]=xb.x+inv6*pb.x; v[5]=xb.y+inv6*pb.y; v[6]=xb.z+inv6*pb.z; v[7]=xb.w+inv6*pb.w;
    }
    {
        float s = 0.0f;
#pragma unroll
        for (int i = 0; i < 8; i++) s += v[i];
        const float mu = block_reduce_sum(s, sbuf) * invD;
        float q = 0.0f;
#pragma unroll
        for (int i = 0; i < 8; i++) { const float c = v[i] - mu; q += c * c; }
        const float rs = rsqrtf(block_reduce_sum(q, sbuf) * invD + 1e-5f);
#pragma unroll
        for (int i = 0; i < 8; i++) v[i] = (v[i] - mu) * rs * g[i] + be[i];
    }
    if (t != 0 && t != T_ - 1) {
        const size_t nb = base + D_;
        const float4 pa = ldP4(P + nb + d0);
        const float4 pb = ldP4(P + nb + d1);
        v[0]+=inv6*pa.x; v[1]+=inv6*pa.y; v[2]+=inv6*pa.z; v[3]+=inv6*pa.w;
        v[4]+=inv6*pb.x; v[5]+=inv6*pb.y; v[6]+=inv6*pb.z; v[7]+=inv6*pb.w;
        float s = 0.0f;
#pragma unroll
        for (int i = 0; i < 8; i++) s += v[i];
        const float mu = block_reduce_sum(s, sbuf) * invD;
        float q = 0.0f;
#pragma unroll
        for (int i = 0; i < 8; i++) { const float c = v[i] - mu; q += c * c; }
        const float rs = rsqrtf(block_reduce_sum(q, sbuf) * invD + 1e-5f);
#pragma unroll
        for (int i = 0; i < 8; i++) v[i] = (v[i] - mu) * rs * g[i] + be[i];
    }
    *reinterpret_cast<float4*>(out + base + d0) = make_float4(v[0], v[1], v[2], v[3]);
    *reinterpret_cast<float4*>(out + base + d1) = make_float4(v[4], v[5], v[6], v[7]);
}

// ---------------------------------------------------------------------------
// Launch. Inputs: x, W1, b1, W2, b2, Wp, bp, gamma, beta.
// W1/b1/W2/b2 dead: mean(softmax(logits)) over the softmax axis == 1/6 exactly.
// ---------------------------------------------------------------------------
extern "C" void kernel_launch(void* const* d_in, const int* in_sizes, int n_in,
                              void* d_out, int out_size) {
    const float* x     = (const float*)d_in[0];
    const float* Wp    = (const float*)d_in[5];
    const float* bp    = (const float*)d_in[6];
    const float* gamma = (const float*)d_in[7];
    const float* beta  = (const float*)d_in[8];
    float* out = (float*)d_out;

    __half* P;
    cudaGetSymbolAddress((void**)&P, g_Ph);

    cudaFuncSetAttribute(braid_gemm_mma, cudaFuncAttributeMaxDynamicSharedMemorySize, SMEM_BYTES);

    dim3 ggrid(D_ / BN, M_ / BM);   // (8, 128): x-fastest -> A-tile L2 reuse, W L2-resident
    braid_gemm_mma<<<ggrid, 256, SMEM_BYTES>>>(x, Wp, bp, P);
    braid_epilogue_kernel<<<M_, 256>>>(x, P, gamma, beta, out);
}